// round 1
// baseline (speedup 1.0000x reference)
#include <cuda_runtime.h>

#define NN 400000
#define NE 2400000
#define FT 30
#define NPG 40
#define NG (NN / NPG)

// Scratch (allocation-free contract: __device__ globals)
__device__ __align__(16) float g_deg_out[NN];
__device__ __align__(16) float g_deg_in[NN];
__device__ __align__(16) float g_h[(size_t)NN * FT];
__device__ __align__(16) float g_agg[(size_t)NN * FT];

// ---------------------------------------------------------------------------
// Zero agg + degree arrays (agg via float4)
// ---------------------------------------------------------------------------
__global__ void k_zero() {
    int stride = gridDim.x * blockDim.x;
    int tid = blockIdx.x * blockDim.x + threadIdx.x;
    float4* a4 = (float4*)g_agg;
    const int n4 = NN * FT / 4;
    float4 z = make_float4(0.f, 0.f, 0.f, 0.f);
    for (int i = tid; i < n4; i += stride) a4[i] = z;
    for (int i = tid; i < NN; i += stride) {
        g_deg_out[i] = 0.f;
        g_deg_in[i] = 0.f;
    }
}

// ---------------------------------------------------------------------------
// Degree counts: deg_out[src]++, deg_in[dst]++
// ---------------------------------------------------------------------------
__global__ void k_deg(const int* __restrict__ src, const int* __restrict__ dst) {
    int i = blockIdx.x * blockDim.x + threadIdx.x;
    if (i < NE) {
        atomicAdd(&g_deg_out[src[i]], 1.f);
        atomicAdd(&g_deg_in[dst[i]], 1.f);
    }
}

// ---------------------------------------------------------------------------
// h[i,:] = (x[i,:] * rsqrt(max(deg_out,1))) @ W       [N, 30]
// Block of 256 threads = 256 nodes; x staged in shared (pad 31 to kill bank
// conflicts), W (900 floats) in shared with broadcast reads, output staged
// back through shared for coalesced stores.
// ---------------------------------------------------------------------------
__global__ __launch_bounds__(256) void k_feat(const float* __restrict__ X,
                                              const float* __restrict__ W) {
    __shared__ float Ws[FT * FT];
    __shared__ float xs[256 * 31];
    int tid = threadIdx.x;
    for (int i = tid; i < FT * FT; i += 256) Ws[i] = W[i];
    int base_node = blockIdx.x * 256;
    int nNodes = NN - base_node;
    if (nNodes > 256) nNodes = 256;
    size_t base = (size_t)base_node * FT;
    int cnt = nNodes * FT;
    for (int i = tid; i < cnt; i += 256) xs[(i / FT) * 31 + (i % FT)] = X[base + i];
    __syncthreads();

    float out[FT];
    if (tid < nNodes) {
        float ns = rsqrtf(fmaxf(g_deg_out[base_node + tid], 1.f));
        float x[FT];
#pragma unroll
        for (int k = 0; k < FT; k++) x[k] = xs[tid * 31 + k];
#pragma unroll
        for (int j = 0; j < FT; j++) {
            float acc = 0.f;
#pragma unroll
            for (int k = 0; k < FT; k++) acc = fmaf(x[k], Ws[k * FT + j], acc);
            out[j] = acc * ns;  // (x*ns)@W == ns*(x@W)
        }
    }
    __syncthreads();
    if (tid < nNodes) {
#pragma unroll
        for (int j = 0; j < FT; j++) xs[tid * 31 + j] = out[j];
    }
    __syncthreads();
    for (int i = tid; i < cnt; i += 256) g_h[base + i] = xs[(i / FT) * 31 + (i % FT)];
}

// ---------------------------------------------------------------------------
// agg[dst,:] += h[src,:]   — thread per (edge, float2 pair): 15 pairs/edge.
// Consecutive threads cover one edge's 120B row => coalesced gather and
// coalesced vectored RED (red.global.add.v2.f32, sm_90+).
// ---------------------------------------------------------------------------
__global__ void k_scatter(const int* __restrict__ src, const int* __restrict__ dst) {
    long long t = (long long)blockIdx.x * blockDim.x + threadIdx.x;
    if (t >= (long long)NE * 15) return;
    int e = (int)(t / 15);
    int p = (int)(t - (long long)e * 15);
    int s = __ldg(src + e);
    int d = __ldg(dst + e);
    float2 v = __ldg((const float2*)g_h + (size_t)s * 15 + p);
    float2* addr = (float2*)g_agg + (size_t)d * 15 + p;
    asm volatile("red.global.add.v2.f32 [%0], {%1, %2};" ::"l"(addr), "f"(v.x), "f"(v.y)
                 : "memory");
}

// ---------------------------------------------------------------------------
// Per-graph: pooled[j] = max_n (agg[n,j]*rsqrt(max(deg_in,1)) + b[j]) over the
// graph's 40 contiguous nodes; then z = relu(pooled@W2+b2); out = sigmoid(z@W3+b3).
// One warp per graph, 8 graphs per 256-thread block.
// ---------------------------------------------------------------------------
__global__ __launch_bounds__(256) void k_pool(const float* __restrict__ b1,
                                              const float* __restrict__ W2,
                                              const float* __restrict__ b2,
                                              const float* __restrict__ W3,
                                              const float* __restrict__ b3,
                                              float* __restrict__ out) {
    __shared__ float bs[FT], W2s[FT * 10], b2s[10], W3s[10 * 4], b3s[4];
    __shared__ float pool[8][32];
    __shared__ float zs[8][16];
    int tid = threadIdx.x;
    if (tid < FT) bs[tid] = b1[tid];
    for (int i = tid; i < FT * 10; i += 256) W2s[i] = W2[i];
    if (tid < 10) b2s[tid] = b2[tid];
    if (tid < 40) W3s[tid] = W3[tid];
    if (tid < 4) b3s[tid] = b3[tid];
    __syncthreads();

    int warp = tid >> 5, lane = tid & 31;
    int g = blockIdx.x * 8 + warp;
    if (g >= NG) return;

    if (lane < FT) {
        float m = -3.402823466e38f;
        int node0 = g * NPG;
        for (int n = 0; n < NPG; n++) {
            int node = node0 + n;
            float nd = rsqrtf(fmaxf(__ldg(&g_deg_in[node]), 1.f));
            float v = g_agg[(size_t)node * FT + lane] * nd + bs[lane];
            m = fmaxf(m, v);
        }
        pool[warp][lane] = m;
    }
    __syncwarp();
    if (lane < 10) {
        float acc = b2s[lane];
#pragma unroll
        for (int k = 0; k < FT; k++) acc = fmaf(pool[warp][k], W2s[k * 10 + lane], acc);
        zs[warp][lane] = fmaxf(acc, 0.f);
    }
    __syncwarp();
    if (lane < 4) {
        float acc = b3s[lane];
#pragma unroll
        for (int k = 0; k < 10; k++) acc = fmaf(zs[warp][k], W3s[k * 4 + lane], acc);
        out[g * 4 + lane] = 1.f / (1.f + expf(-acc));
    }
}

// ---------------------------------------------------------------------------
// Launch: size-based input dispatch (robust to scalar num_graphs presence)
// ---------------------------------------------------------------------------
extern "C" void kernel_launch(void* const* d_in, const int* in_sizes, int n_in,
                              void* d_out, int out_size) {
    const float *X = 0, *W = 0, *b1 = 0, *W2 = 0, *b2 = 0, *W3 = 0, *b3 = 0;
    const int *src = 0, *dst = 0;
    for (int i = 0; i < n_in; i++) {
        int s = in_sizes[i];
        void* p = d_in[i];
        switch (s) {
            case NN * FT: X = (const float*)p; break;
            case NE:
                if (!src) src = (const int*)p;
                else dst = (const int*)p;
                break;
            case FT * FT: W = (const float*)p; break;
            case FT: b1 = (const float*)p; break;
            case FT * 10: W2 = (const float*)p; break;
            case 10: b2 = (const float*)p; break;
            case 40: W3 = (const float*)p; break;
            case 4: b3 = (const float*)p; break;
            default: break;  // segment_ids (NN), num_graphs (1) unused
        }
    }
    float* out = (float*)d_out;

    k_zero<<<2048, 256>>>();
    k_deg<<<(NE + 255) / 256, 256>>>(src, dst);
    k_feat<<<(NN + 255) / 256, 256>>>(X, W);
    long long pairs = (long long)NE * 15;
    k_scatter<<<(unsigned)((pairs + 255) / 256), 256>>>(src, dst);
    k_pool<<<(NG + 7) / 8, 256>>>(b1, W2, b2, W3, b3, out);
}

// round 2
// speedup vs baseline: 1.1508x; 1.1508x over previous
#include <cuda_runtime.h>

#define NN 400000
#define NE 2400000
#define FT 30
#define FP 32          // padded row stride (floats) -> 128B per row
#define NPG 40
#define NG (NN / NPG)

// Scratch (allocation-free contract: __device__ globals). Rows padded to 32
// floats so each node row is exactly one 128B cache line.
__device__ __align__(16) float g_deg_out[NN];
__device__ __align__(16) float g_deg_in[NN];
__device__ __align__(16) float g_h[(size_t)NN * FP];
__device__ __align__(16) float g_agg[(size_t)NN * FP];

// ---------------------------------------------------------------------------
// Zero agg (padded) + degree arrays
// ---------------------------------------------------------------------------
__global__ void k_zero() {
    int stride = gridDim.x * blockDim.x;
    int tid = blockIdx.x * blockDim.x + threadIdx.x;
    float4* a4 = (float4*)g_agg;
    const int n4 = NN * FP / 4;
    float4 z = make_float4(0.f, 0.f, 0.f, 0.f);
    for (int i = tid; i < n4; i += stride) a4[i] = z;
    for (int i = tid; i < NN; i += stride) {
        g_deg_out[i] = 0.f;
        g_deg_in[i] = 0.f;
    }
}

// ---------------------------------------------------------------------------
// Degree counts: 4 edges per thread via int4
// ---------------------------------------------------------------------------
__global__ void k_deg(const int4* __restrict__ src4, const int4* __restrict__ dst4) {
    int i = blockIdx.x * blockDim.x + threadIdx.x;
    if (i < NE / 4) {
        int4 s = __ldg(src4 + i);
        int4 d = __ldg(dst4 + i);
        atomicAdd(&g_deg_out[s.x], 1.f);
        atomicAdd(&g_deg_out[s.y], 1.f);
        atomicAdd(&g_deg_out[s.z], 1.f);
        atomicAdd(&g_deg_out[s.w], 1.f);
        atomicAdd(&g_deg_in[d.x], 1.f);
        atomicAdd(&g_deg_in[d.y], 1.f);
        atomicAdd(&g_deg_in[d.z], 1.f);
        atomicAdd(&g_deg_in[d.w], 1.f);
    }
}

// ---------------------------------------------------------------------------
// h[i,0:30] = (x[i,:] * rsqrt(max(deg_out,1))) @ W ; h[i,30:32] = 0
// 256 nodes per block; X staged via smem (32-padded), output written via float4.
// ---------------------------------------------------------------------------
__global__ __launch_bounds__(256) void k_feat(const float* __restrict__ X,
                                              const float* __restrict__ W) {
    __shared__ float Ws[FT * FT];
    __shared__ float xs[256 * FP];
    int tid = threadIdx.x;
    for (int i = tid; i < FT * FT; i += 256) Ws[i] = W[i];
    int base_node = blockIdx.x * 256;
    int nNodes = NN - base_node;
    if (nNodes > 256) nNodes = 256;
    int cnt = nNodes * FT;
    size_t baseX = (size_t)base_node * FT;
    for (int i = tid; i < cnt; i += 256) xs[(i / FT) * FP + (i % FT)] = X[baseX + i];
    __syncthreads();

    float out[FT];
    if (tid < nNodes) {
        float ns = rsqrtf(fmaxf(g_deg_out[base_node + tid], 1.f));
        float x[FT];
#pragma unroll
        for (int k = 0; k < FT; k++) x[k] = xs[tid * FP + k];
#pragma unroll
        for (int j = 0; j < FT; j++) {
            float acc = 0.f;
#pragma unroll
            for (int k = 0; k < FT; k++) acc = fmaf(x[k], Ws[k * FT + j], acc);
            out[j] = acc * ns;
        }
    }
    __syncthreads();
    if (tid < nNodes) {
#pragma unroll
        for (int j = 0; j < FT; j++) xs[tid * FP + j] = out[j];
        xs[tid * FP + 30] = 0.f;
        xs[tid * FP + 31] = 0.f;
    }
    __syncthreads();
    // coalesced float4 store of padded rows
    float4* h4 = (float4*)(g_h + (size_t)base_node * FP);
    const float4* xs4 = (const float4*)xs;
    int cnt4 = nNodes * (FP / 4);
    for (int i = tid; i < cnt4; i += 256) h4[i] = xs4[i];
}

// ---------------------------------------------------------------------------
// agg[dst,:] += h[src,:] — 8 threads per edge, float4 per thread.
// One LDG.128 gather + one red.global.add.v4.f32 per thread; each row is one
// aligned 128B line.
// ---------------------------------------------------------------------------
__global__ void k_scatter(const int* __restrict__ src, const int* __restrict__ dst) {
    unsigned t = blockIdx.x * blockDim.x + threadIdx.x;  // < NE*8 = 19.2M
    if (t >= (unsigned)NE * 8u) return;
    int e = t >> 3;
    int p = t & 7;
    int s = __ldg(src + e);
    int d = __ldg(dst + e);
    float4 v = __ldg((const float4*)g_h + ((size_t)s << 3) + p);
    float4* addr = (float4*)g_agg + ((size_t)d << 3) + p;
    asm volatile("red.global.add.v4.f32 [%0], {%1, %2, %3, %4};" ::"l"(addr),
                 "f"(v.x), "f"(v.y), "f"(v.z), "f"(v.w)
                 : "memory");
}

// ---------------------------------------------------------------------------
// Per-graph max-pool over 40 contiguous nodes, then MLP head.
// One warp per graph, 8 graphs per block.
// ---------------------------------------------------------------------------
__global__ __launch_bounds__(256) void k_pool(const float* __restrict__ b1,
                                              const float* __restrict__ W2,
                                              const float* __restrict__ b2,
                                              const float* __restrict__ W3,
                                              const float* __restrict__ b3,
                                              float* __restrict__ out) {
    __shared__ float bs[FT], W2s[FT * 10], b2s[10], W3s[10 * 4], b3s[4];
    __shared__ float pool[8][32];
    __shared__ float zs[8][16];
    int tid = threadIdx.x;
    if (tid < FT) bs[tid] = b1[tid];
    for (int i = tid; i < FT * 10; i += 256) W2s[i] = W2[i];
    if (tid < 10) b2s[tid] = b2[tid];
    if (tid < 40) W3s[tid] = W3[tid];
    if (tid < 4) b3s[tid] = b3[tid];
    __syncthreads();

    int warp = tid >> 5, lane = tid & 31;
    int g = blockIdx.x * 8 + warp;
    if (g >= NG) return;

    if (lane < FT) {
        float m = -3.402823466e38f;
        int node0 = g * NPG;
#pragma unroll 4
        for (int n = 0; n < NPG; n++) {
            int node = node0 + n;
            float nd = rsqrtf(fmaxf(__ldg(&g_deg_in[node]), 1.f));
            float v = g_agg[((size_t)node << 5) + lane] * nd + bs[lane];
            m = fmaxf(m, v);
        }
        pool[warp][lane] = m;
    }
    __syncwarp();
    if (lane < 10) {
        float acc = b2s[lane];
#pragma unroll
        for (int k = 0; k < FT; k++) acc = fmaf(pool[warp][k], W2s[k * 10 + lane], acc);
        zs[warp][lane] = fmaxf(acc, 0.f);
    }
    __syncwarp();
    if (lane < 4) {
        float acc = b3s[lane];
#pragma unroll
        for (int k = 0; k < 10; k++) acc = fmaf(zs[warp][k], W3s[k * 4 + lane], acc);
        out[g * 4 + lane] = 1.f / (1.f + expf(-acc));
    }
}

// ---------------------------------------------------------------------------
// Launch
// ---------------------------------------------------------------------------
extern "C" void kernel_launch(void* const* d_in, const int* in_sizes, int n_in,
                              void* d_out, int out_size) {
    const float *X = 0, *W = 0, *b1 = 0, *W2 = 0, *b2 = 0, *W3 = 0, *b3 = 0;
    const int *src = 0, *dst = 0;
    for (int i = 0; i < n_in; i++) {
        int s = in_sizes[i];
        void* p = d_in[i];
        switch (s) {
            case NN * FT: X = (const float*)p; break;
            case NE:
                if (!src) src = (const int*)p;
                else dst = (const int*)p;
                break;
            case FT * FT: W = (const float*)p; break;
            case FT: b1 = (const float*)p; break;
            case FT * 10: W2 = (const float*)p; break;
            case 10: b2 = (const float*)p; break;
            case 40: W3 = (const float*)p; break;
            case 4: b3 = (const float*)p; break;
            default: break;  // segment_ids (NN), num_graphs (1) unused
        }
    }
    float* out = (float*)d_out;

    k_zero<<<2048, 256>>>();
    k_deg<<<(NE / 4 + 255) / 256, 256>>>((const int4*)src, (const int4*)dst);
    k_feat<<<(NN + 255) / 256, 256>>>(X, W);
    unsigned total = (unsigned)NE * 8u;
    k_scatter<<<(total + 255) / 256, 256>>>(src, dst);
    k_pool<<<(NG + 7) / 8, 256>>>(b1, W2, b2, W3, b3, out);
}

// round 3
// speedup vs baseline: 1.1948x; 1.0383x over previous
#include <cuda_runtime.h>

#define NN 400000
#define NE 2400000
#define FT 30
#define FP 32          // padded row stride (floats) -> 128B per row
#define NPG 40
#define NG (NN / NPG)

#define SCAN_TILE 2048
#define SCAN_NBLK ((NN + SCAN_TILE - 1) / SCAN_TILE)  // 196

// Scratch (allocation-free contract: __device__ globals)
__device__ int g_deg_out[NN];
__device__ int g_deg_in[NN];
__device__ int g_rowptr[NN];
__device__ int g_cursor[NN];
__device__ int g_part[SCAN_NBLK];
__device__ int g_adj[NE];
__device__ __align__(16) float g_h[(size_t)NN * FP];

// ---------------------------------------------------------------------------
// Zero degree arrays (int)
// ---------------------------------------------------------------------------
__global__ void k_zero() {
    int i = blockIdx.x * blockDim.x + threadIdx.x;
    if (i < NN) {
        g_deg_out[i] = 0;
        g_deg_in[i] = 0;
    }
}

// ---------------------------------------------------------------------------
// Degree counts: 4 edges per thread via int4
// ---------------------------------------------------------------------------
__global__ void k_deg(const int4* __restrict__ src4, const int4* __restrict__ dst4) {
    int i = blockIdx.x * blockDim.x + threadIdx.x;
    if (i < NE / 4) {
        int4 s = __ldg(src4 + i);
        int4 d = __ldg(dst4 + i);
        atomicAdd(&g_deg_out[s.x], 1);
        atomicAdd(&g_deg_out[s.y], 1);
        atomicAdd(&g_deg_out[s.z], 1);
        atomicAdd(&g_deg_out[s.w], 1);
        atomicAdd(&g_deg_in[d.x], 1);
        atomicAdd(&g_deg_in[d.y], 1);
        atomicAdd(&g_deg_in[d.z], 1);
        atomicAdd(&g_deg_in[d.w], 1);
    }
}

// ---------------------------------------------------------------------------
// Prefix scan of deg_in -> rowptr (3 stages)
// ---------------------------------------------------------------------------
__global__ __launch_bounds__(256) void k_scan1() {
    __shared__ int s[256];
    int t = threadIdx.x;
    int base = blockIdx.x * SCAN_TILE + t * 8;
    int v[8];
    int tot = 0;
#pragma unroll
    for (int k = 0; k < 8; k++) {
        int idx = base + k;
        v[k] = (idx < NN) ? g_deg_in[idx] : 0;
        tot += v[k];
    }
    s[t] = tot;
    __syncthreads();
#pragma unroll
    for (int off = 1; off < 256; off <<= 1) {
        int x = (t >= off) ? s[t - off] : 0;
        __syncthreads();
        s[t] += x;
        __syncthreads();
    }
    int excl = s[t] - tot;  // exclusive prefix of this thread's chunk
    int run = excl;
#pragma unroll
    for (int k = 0; k < 8; k++) {
        int idx = base + k;
        if (idx < NN) g_rowptr[idx] = run;
        run += v[k];
    }
    if (t == 255) g_part[blockIdx.x] = s[255];  // block total
}

__global__ __launch_bounds__(256) void k_scan2() {
    __shared__ int s[256];
    int t = threadIdx.x;
    int val = (t < SCAN_NBLK) ? g_part[t] : 0;
    s[t] = val;
    __syncthreads();
#pragma unroll
    for (int off = 1; off < 256; off <<= 1) {
        int x = (t >= off) ? s[t - off] : 0;
        __syncthreads();
        s[t] += x;
        __syncthreads();
    }
    if (t < SCAN_NBLK) g_part[t] = s[t] - val;  // exclusive
}

__global__ void k_scan3() {
    int i = blockIdx.x * blockDim.x + threadIdx.x;
    if (i < NN) {
        int r = g_rowptr[i] + g_part[i / SCAN_TILE];
        g_rowptr[i] = r;
        g_cursor[i] = r;
    }
}

// ---------------------------------------------------------------------------
// Bucket fill: adj[pos] = src[e] grouped by dst
// ---------------------------------------------------------------------------
__global__ void k_fill(const int* __restrict__ src, const int* __restrict__ dst) {
    int e = blockIdx.x * blockDim.x + threadIdx.x;
    if (e < NE) {
        int d = __ldg(dst + e);
        int pos = atomicAdd(&g_cursor[d], 1);
        g_adj[pos] = __ldg(src + e);
    }
}

// ---------------------------------------------------------------------------
// h[i,0:30] = (x[i,:] * rsqrt(max(deg_out,1))) @ W ; h[i,30:32] = 0
// ---------------------------------------------------------------------------
__global__ __launch_bounds__(256) void k_feat(const float* __restrict__ X,
                                              const float* __restrict__ W) {
    __shared__ float Ws[FT * FT];
    __shared__ float xs[256 * FP];
    int tid = threadIdx.x;
    for (int i = tid; i < FT * FT; i += 256) Ws[i] = W[i];
    int base_node = blockIdx.x * 256;
    int nNodes = NN - base_node;
    if (nNodes > 256) nNodes = 256;
    int cnt = nNodes * FT;
    size_t baseX = (size_t)base_node * FT;
    for (int i = tid; i < cnt; i += 256) xs[(i / FT) * FP + (i % FT)] = X[baseX + i];
    __syncthreads();

    float out[FT];
    if (tid < nNodes) {
        float ns = rsqrtf(fmaxf((float)g_deg_out[base_node + tid], 1.f));
        float x[FT];
#pragma unroll
        for (int k = 0; k < FT; k++) x[k] = xs[tid * FP + k];
#pragma unroll
        for (int j = 0; j < FT; j++) {
            float acc = 0.f;
#pragma unroll
            for (int k = 0; k < FT; k++) acc = fmaf(x[k], Ws[k * FT + j], acc);
            out[j] = acc * ns;
        }
    }
    __syncthreads();
    if (tid < nNodes) {
#pragma unroll
        for (int j = 0; j < FT; j++) xs[tid * FP + j] = out[j];
        xs[tid * FP + 30] = 0.f;
        xs[tid * FP + 31] = 0.f;
    }
    __syncthreads();
    float4* h4 = (float4*)(g_h + (size_t)base_node * FP);
    const float4* xs4 = (const float4*)xs;
    int cnt4 = nNodes * (FP / 4);
    for (int i = tid; i < cnt4; i += 256) h4[i] = xs4[i];
}

// ---------------------------------------------------------------------------
// Fused gather + max-pool + MLP head. One block (320 threads) per graph.
// Each 8-thread group owns one node: gathers h[adj] rows (float4/thread),
// register-accumulates, applies rsqrt(deg_in)+bias, stages to smem;
// then 32-lane feature-max over 40 nodes; then the tiny MLP.
// ---------------------------------------------------------------------------
__global__ __launch_bounds__(320) void k_gatherpool(const float* __restrict__ b1,
                                                    const float* __restrict__ W2,
                                                    const float* __restrict__ b2,
                                                    const float* __restrict__ W3,
                                                    const float* __restrict__ b3,
                                                    float* __restrict__ out) {
    __shared__ float stage[NPG][FP];
    __shared__ float bs[FP];
    __shared__ float W2s[FT * 10], b2s[10], W3s[10 * 4], b3s[4];
    __shared__ float pool[FP], zs[16];
    int tid = threadIdx.x;
    if (tid < FP) bs[tid] = (tid < FT) ? b1[tid] : 0.f;
    for (int i = tid; i < FT * 10; i += 320) W2s[i] = W2[i];
    if (tid >= 64 && tid < 74) b2s[tid - 64] = b2[tid - 64];
    if (tid >= 96 && tid < 136) W3s[tid - 96] = W3[tid - 96];
    if (tid >= 160 && tid < 164) b3s[tid - 160] = b3[tid - 160];

    int n = tid >> 3;   // node within graph, 0..39
    int p = tid & 7;    // float4 slot, 0..7
    int node = blockIdx.x * NPG + n;
    int start = __ldg(&g_rowptr[node]);
    int dg = __ldg(&g_deg_in[node]);

    float4 acc = make_float4(0.f, 0.f, 0.f, 0.f);
    const float4* h4 = (const float4*)g_h;
    for (int k = 0; k < dg; k++) {
        int s = __ldg(&g_adj[start + k]);
        float4 v = __ldg(h4 + ((size_t)s << 3) + p);
        acc.x += v.x;
        acc.y += v.y;
        acc.z += v.z;
        acc.w += v.w;
    }
    float nd = rsqrtf(fmaxf((float)dg, 1.f));
    __syncthreads();  // bs ready
    float4 bb = ((const float4*)bs)[p];
    stage[n][4 * p + 0] = fmaf(acc.x, nd, bb.x);
    stage[n][4 * p + 1] = fmaf(acc.y, nd, bb.y);
    stage[n][4 * p + 2] = fmaf(acc.z, nd, bb.z);
    stage[n][4 * p + 3] = fmaf(acc.w, nd, bb.w);
    __syncthreads();

    if (tid < FP) {
        float m = -3.402823466e38f;
#pragma unroll 8
        for (int q = 0; q < NPG; q++) m = fmaxf(m, stage[q][tid]);
        pool[tid] = m;
    }
    __syncthreads();
    if (tid < 10) {
        float a = b2s[tid];
#pragma unroll
        for (int k = 0; k < FT; k++) a = fmaf(pool[k], W2s[k * 10 + tid], a);
        zs[tid] = fmaxf(a, 0.f);
    }
    __syncthreads();
    if (tid < 4) {
        float a = b3s[tid];
#pragma unroll
        for (int k = 0; k < 10; k++) a = fmaf(zs[k], W3s[k * 4 + tid], a);
        out[blockIdx.x * 4 + tid] = 1.f / (1.f + expf(-a));
    }
}

// ---------------------------------------------------------------------------
// Launch
// ---------------------------------------------------------------------------
extern "C" void kernel_launch(void* const* d_in, const int* in_sizes, int n_in,
                              void* d_out, int out_size) {
    const float *X = 0, *W = 0, *b1 = 0, *W2 = 0, *b2 = 0, *W3 = 0, *b3 = 0;
    const int *src = 0, *dst = 0;
    for (int i = 0; i < n_in; i++) {
        int s = in_sizes[i];
        void* p = d_in[i];
        switch (s) {
            case NN * FT: X = (const float*)p; break;
            case NE:
                if (!src) src = (const int*)p;
                else dst = (const int*)p;
                break;
            case FT * FT: W = (const float*)p; break;
            case FT: b1 = (const float*)p; break;
            case FT * 10: W2 = (const float*)p; break;
            case 10: b2 = (const float*)p; break;
            case 40: W3 = (const float*)p; break;
            case 4: b3 = (const float*)p; break;
            default: break;  // segment_ids (NN), num_graphs (1) unused
        }
    }
    float* out = (float*)d_out;

    k_zero<<<(NN + 255) / 256, 256>>>();
    k_deg<<<(NE / 4 + 255) / 256, 256>>>((const int4*)src, (const int4*)dst);
    k_scan1<<<SCAN_NBLK, 256>>>();
    k_scan2<<<1, 256>>>();
    k_scan3<<<(NN + 255) / 256, 256>>>();
    k_fill<<<(NE + 255) / 256, 256>>>(src, dst);
    k_feat<<<(NN + 255) / 256, 256>>>(X, W);
    k_gatherpool<<<NG, 320>>>(b1, W2, b2, W3, b3, out);
}

// round 4
// speedup vs baseline: 1.2354x; 1.0340x over previous
#include <cuda_runtime.h>

#define NN 400000
#define NE 2400000
#define FT 30
#define FP 32          // padded row stride (floats) -> 128B per row
#define NPG 40
#define NG (NN / NPG)

#define SCAN_TILE 2048
#define SCAN_NBLK ((NN + SCAN_TILE - 1) / SCAN_TILE)  // 196

#define FEAT_BLOCKS ((NN + 255) / 256)   // 1563
#define FILL_BLOCKS ((NE + 255) / 256)   // 9375

// Scratch (allocation-free contract: __device__ globals)
__device__ int g_deg_out[NN];
__device__ int g_deg_in[NN];
__device__ int g_rowptr[NN];
__device__ int g_cursor[NN];
__device__ int g_part[SCAN_NBLK];
__device__ int g_adj[NE];
__device__ __align__(16) float g_h[(size_t)NN * FP];

// ---------------------------------------------------------------------------
// Zero degree arrays (vectorized)
// ---------------------------------------------------------------------------
__global__ void k_zero() {
    int i = blockIdx.x * blockDim.x + threadIdx.x;
    int4 z = make_int4(0, 0, 0, 0);
    if (i < NN / 4) {
        ((int4*)g_deg_out)[i] = z;
        ((int4*)g_deg_in)[i] = z;
    }
}

// ---------------------------------------------------------------------------
// Degree counts: 4 edges per thread via int4
// ---------------------------------------------------------------------------
__global__ void k_deg(const int4* __restrict__ src4, const int4* __restrict__ dst4) {
    int i = blockIdx.x * blockDim.x + threadIdx.x;
    if (i < NE / 4) {
        int4 s = __ldg(src4 + i);
        int4 d = __ldg(dst4 + i);
        atomicAdd(&g_deg_out[s.x], 1);
        atomicAdd(&g_deg_out[s.y], 1);
        atomicAdd(&g_deg_out[s.z], 1);
        atomicAdd(&g_deg_out[s.w], 1);
        atomicAdd(&g_deg_in[d.x], 1);
        atomicAdd(&g_deg_in[d.y], 1);
        atomicAdd(&g_deg_in[d.z], 1);
        atomicAdd(&g_deg_in[d.w], 1);
    }
}

// ---------------------------------------------------------------------------
// Scan stage 1: per-2048-tile local exclusive prefix + tile totals
// ---------------------------------------------------------------------------
__global__ __launch_bounds__(256) void k_scan1() {
    __shared__ int s[256];
    int t = threadIdx.x;
    int base = blockIdx.x * SCAN_TILE + t * 8;
    int v[8];
    int tot = 0;
#pragma unroll
    for (int k = 0; k < 8; k++) {
        int idx = base + k;
        v[k] = (idx < NN) ? g_deg_in[idx] : 0;
        tot += v[k];
    }
    s[t] = tot;
    __syncthreads();
#pragma unroll
    for (int off = 1; off < 256; off <<= 1) {
        int x = (t >= off) ? s[t - off] : 0;
        __syncthreads();
        s[t] += x;
        __syncthreads();
    }
    int run = s[t] - tot;  // exclusive prefix of this thread's chunk
#pragma unroll
    for (int k = 0; k < 8; k++) {
        int idx = base + k;
        if (idx < NN) g_rowptr[idx] = run;
        run += v[k];
    }
    if (t == 255) g_part[blockIdx.x] = s[255];
}

// ---------------------------------------------------------------------------
// Scan stage 2+3 fused: every block redundantly scans the 196 partials in
// smem, then applies offsets and initializes cursors.
// ---------------------------------------------------------------------------
__global__ __launch_bounds__(256) void k_scan3() {
    __shared__ int incl[256];
    __shared__ int excl[256];
    int t = threadIdx.x;
    int v = (t < SCAN_NBLK) ? g_part[t] : 0;
    incl[t] = v;
    __syncthreads();
#pragma unroll
    for (int off = 1; off < 256; off <<= 1) {
        int x = (t >= off) ? incl[t - off] : 0;
        __syncthreads();
        incl[t] += x;
        __syncthreads();
    }
    excl[t] = incl[t] - v;
    __syncthreads();
    int i = blockIdx.x * 256 + t;
    if (i < NN) {
        int r = g_rowptr[i] + excl[i >> 11];  // SCAN_TILE == 2048
        g_rowptr[i] = r;
        g_cursor[i] = r;
    }
}

// ---------------------------------------------------------------------------
// Fused fill + feat (independent stages; co-residency hides fill's
// random-atomic latency under feat's streaming traffic).
// feat: h[i,0:30] = (x[i,:]*rsqrt(max(deg_out,1))) @ W ; h[i,30:32]=0
// fill: adj[pos] = src[e], grouped by dst via cursor atomics
// ---------------------------------------------------------------------------
__global__ __launch_bounds__(256) void k_fillfeat(const float* __restrict__ X,
                                                  const float* __restrict__ W,
                                                  const int* __restrict__ src,
                                                  const int* __restrict__ dst) {
    __shared__ float Ws[FT * FT];
    __shared__ float xs[256 * FP];
    int tid = threadIdx.x;
    int b = blockIdx.x;
    if (b < FEAT_BLOCKS) {
        for (int i = tid; i < FT * FT; i += 256) Ws[i] = W[i];
        int base_node = b * 256;
        int nNodes = NN - base_node;
        if (nNodes > 256) nNodes = 256;
        int cnt = nNodes * FT;
        size_t baseX = (size_t)base_node * FT;
        for (int i = tid; i < cnt; i += 256) xs[(i / FT) * FP + (i % FT)] = X[baseX + i];
        __syncthreads();

        float out[FT];
        if (tid < nNodes) {
            float ns = rsqrtf(fmaxf((float)g_deg_out[base_node + tid], 1.f));
            float x[FT];
#pragma unroll
            for (int k = 0; k < FT; k++) x[k] = xs[tid * FP + k];
#pragma unroll
            for (int j = 0; j < FT; j++) {
                float acc = 0.f;
#pragma unroll
                for (int k = 0; k < FT; k++) acc = fmaf(x[k], Ws[k * FT + j], acc);
                out[j] = acc * ns;
            }
        }
        __syncthreads();
        if (tid < nNodes) {
#pragma unroll
            for (int j = 0; j < FT; j++) xs[tid * FP + j] = out[j];
            xs[tid * FP + 30] = 0.f;
            xs[tid * FP + 31] = 0.f;
        }
        __syncthreads();
        float4* h4 = (float4*)(g_h + (size_t)base_node * FP);
        const float4* xs4 = (const float4*)xs;
        int cnt4 = nNodes * (FP / 4);
        for (int i = tid; i < cnt4; i += 256) h4[i] = xs4[i];
    } else {
        int e = (b - FEAT_BLOCKS) * 256 + tid;
        if (e < NE) {
            int d = __ldg(dst + e);
            int pos = atomicAdd(&g_cursor[d], 1);
            g_adj[pos] = __ldg(src + e);
        }
    }
}

// ---------------------------------------------------------------------------
// Fused gather + max-pool + MLP head. One block (320 threads) per graph.
// 8-thread group per node; 2-way unrolled gather loop for MLP.
// ---------------------------------------------------------------------------
__global__ __launch_bounds__(320) void k_gatherpool(const float* __restrict__ b1,
                                                    const float* __restrict__ W2,
                                                    const float* __restrict__ b2,
                                                    const float* __restrict__ W3,
                                                    const float* __restrict__ b3,
                                                    float* __restrict__ out) {
    __shared__ float stage[NPG][FP];
    __shared__ float bs[FP];
    __shared__ float W2s[FT * 10], b2s[10], W3s[10 * 4], b3s[4];
    __shared__ float pool[FP], zs[16];
    int tid = threadIdx.x;
    if (tid < FP) bs[tid] = (tid < FT) ? b1[tid] : 0.f;
    for (int i = tid; i < FT * 10; i += 320) W2s[i] = W2[i];
    if (tid >= 64 && tid < 74) b2s[tid - 64] = b2[tid - 64];
    if (tid >= 96 && tid < 136) W3s[tid - 96] = W3[tid - 96];
    if (tid >= 160 && tid < 164) b3s[tid - 160] = b3[tid - 160];

    int n = tid >> 3;   // node within graph, 0..39
    int p = tid & 7;    // float4 slot, 0..7
    int node = blockIdx.x * NPG + n;
    int start = __ldg(&g_rowptr[node]);
    int dg = __ldg(&g_deg_in[node]);

    float4 a0 = make_float4(0.f, 0.f, 0.f, 0.f);
    float4 a1 = make_float4(0.f, 0.f, 0.f, 0.f);
    const float4* h4 = (const float4*)g_h;
    int k = 0;
    for (; k + 2 <= dg; k += 2) {
        int s0 = __ldg(&g_adj[start + k]);
        int s1 = __ldg(&g_adj[start + k + 1]);
        float4 v0 = __ldg(h4 + ((size_t)s0 << 3) + p);
        float4 v1 = __ldg(h4 + ((size_t)s1 << 3) + p);
        a0.x += v0.x; a0.y += v0.y; a0.z += v0.z; a0.w += v0.w;
        a1.x += v1.x; a1.y += v1.y; a1.z += v1.z; a1.w += v1.w;
    }
    if (k < dg) {
        int s0 = __ldg(&g_adj[start + k]);
        float4 v0 = __ldg(h4 + ((size_t)s0 << 3) + p);
        a0.x += v0.x; a0.y += v0.y; a0.z += v0.z; a0.w += v0.w;
    }
    a0.x += a1.x; a0.y += a1.y; a0.z += a1.z; a0.w += a1.w;

    float nd = rsqrtf(fmaxf((float)dg, 1.f));
    __syncthreads();  // bs ready
    float4 bb = ((const float4*)bs)[p];
    stage[n][4 * p + 0] = fmaf(a0.x, nd, bb.x);
    stage[n][4 * p + 1] = fmaf(a0.y, nd, bb.y);
    stage[n][4 * p + 2] = fmaf(a0.z, nd, bb.z);
    stage[n][4 * p + 3] = fmaf(a0.w, nd, bb.w);
    __syncthreads();

    if (tid < FP) {
        float m = -3.402823466e38f;
#pragma unroll 8
        for (int q = 0; q < NPG; q++) m = fmaxf(m, stage[q][tid]);
        pool[tid] = m;
    }
    __syncthreads();
    if (tid < 10) {
        float a = b2s[tid];
#pragma unroll
        for (int kk = 0; kk < FT; kk++) a = fmaf(pool[kk], W2s[kk * 10 + tid], a);
        zs[tid] = fmaxf(a, 0.f);
    }
    __syncthreads();
    if (tid < 4) {
        float a = b3s[tid];
#pragma unroll
        for (int kk = 0; kk < 10; kk++) a = fmaf(zs[kk], W3s[kk * 4 + tid], a);
        out[blockIdx.x * 4 + tid] = 1.f / (1.f + expf(-a));
    }
}

// ---------------------------------------------------------------------------
// Launch
// ---------------------------------------------------------------------------
extern "C" void kernel_launch(void* const* d_in, const int* in_sizes, int n_in,
                              void* d_out, int out_size) {
    const float *X = 0, *W = 0, *b1 = 0, *W2 = 0, *b2 = 0, *W3 = 0, *b3 = 0;
    const int *src = 0, *dst = 0;
    for (int i = 0; i < n_in; i++) {
        int s = in_sizes[i];
        void* p = d_in[i];
        switch (s) {
            case NN * FT: X = (const float*)p; break;
            case NE:
                if (!src) src = (const int*)p;
                else dst = (const int*)p;
                break;
            case FT * FT: W = (const float*)p; break;
            case FT: b1 = (const float*)p; break;
            case FT * 10: W2 = (const float*)p; break;
            case 10: b2 = (const float*)p; break;
            case 40: W3 = (const float*)p; break;
            case 4: b3 = (const float*)p; break;
            default: break;  // segment_ids (NN), num_graphs (1) unused
        }
    }
    float* out = (float*)d_out;

    k_zero<<<(NN / 4 + 255) / 256, 256>>>();
    k_deg<<<(NE / 4 + 255) / 256, 256>>>((const int4*)src, (const int4*)dst);
    k_scan1<<<SCAN_NBLK, 256>>>();
    k_scan3<<<(NN + 255) / 256, 256>>>();
    k_fillfeat<<<FEAT_BLOCKS + FILL_BLOCKS, 256>>>(X, W, src, dst);
    k_gatherpool<<<NG, 320>>>(b1, W2, b2, W3, b3, out);
}